// round 14
// baseline (speedup 1.0000x reference)
#include <cuda_runtime.h>
#include <float.h>

#define N 16384
#define H 64
#define EPSF 1e-8f
#define GRID 64
#define TPB 256
#define NW (TPB / 32)      // 8 warps
#define NB 65536           // buckets = top 16 bits of order-preserving key
#define NCOARSE 64         // 1024 buckets per coarse bin == one block's range

// ---------------- scratch (device globals; no allocation allowed) ------------
__device__ __align__(16) unsigned g_tmpk[N];      // bucket-grouped keys
__device__ __align__(16) unsigned g_sortedk[N];   // fully sorted keys
__device__ __align__(16) int g_cnt[NB];           // INVARIANT: zero at entry; re-zeroed phase 2
__device__ __align__(16) int g_start[NB + 4];     // bucket starts; [NB] = N
__device__ __align__(16) int g_coarse[NCOARSE];   // INVARIANT: zero at entry; re-zeroed phase 2
__device__ float g_pmse[GRID], g_pd2[GRID], g_pdens[GRID], g_pdmax[GRID];
__device__ unsigned g_arrive = 0;  // barrier arrival counter (self-resetting)
__device__ unsigned g_epoch  = 0;  // barrier epoch (monotonic, wrap-safe)
__device__ unsigned g_done   = 0;  // finalize counter (self-resetting)

// ---------------- helpers -----------------------------------------------------
__device__ __forceinline__ float warp_sum(float v) {
#pragma unroll
    for (int o = 16; o > 0; o >>= 1) v += __shfl_xor_sync(0xffffffffu, v, o);
    return v;
}
__device__ __forceinline__ float warp_max(float v) {
#pragma unroll
    for (int o = 16; o > 0; o >>= 1) v = fmaxf(v, __shfl_xor_sync(0xffffffffu, v, o));
    return v;
}
__device__ __forceinline__ int warp_sumi(int v) {
#pragma unroll
    for (int o = 16; o > 0; o >>= 1) v += __shfl_xor_sync(0xffffffffu, v, o);
    return v;
}
__device__ __forceinline__ unsigned int okey(float f) {
    unsigned int u = __float_as_uint(f);
    return (u & 0x80000000u) ? ~u : (u | 0x80000000u);
}
__device__ __forceinline__ float inv_okey(unsigned k) {
    unsigned u = (k & 0x80000000u) ? (k ^ 0x80000000u) : ~k;
    return __uint_as_float(u);
}

// grid-wide flat barrier: all GRID blocks co-resident (GRID=64 < 148 SMs).
// __threadfence orders writes into L2 AND emits CCTL.IVALL (own-L1 invalidate),
// so post-barrier plain loads refetch fresh data from L2.
__device__ __forceinline__ void grid_sync(unsigned base, unsigned ph) {
    __syncthreads();
    if (threadIdx.x == 0) {
        __threadfence();
        unsigned a = atomicAdd(&g_arrive, 1);
        if (a == GRID - 1) {
            atomicExch(&g_arrive, 0);
            __threadfence();
            atomicAdd(&g_epoch, 1);     // release
        } else {
            while ((*(volatile unsigned*)&g_epoch) - base < ph) { }
        }
    }
    __syncthreads();
}

__global__ void __launch_bounds__(TPB, 1)
fused_kernel(const float* __restrict__ x,   const float* __restrict__ tgt,
             const float* __restrict__ w1,  const float* __restrict__ b1,
             const float* __restrict__ w2,  const float* __restrict__ b2,
             float* __restrict__ out) {
    __shared__ float sw1x2[H], sb1x2[H], sw2[H], sc2[H];
    __shared__ float sA[NW], sB[NW];
    __shared__ int   sI[NW];
    __shared__ int   scoarse[NCOARSE];
    __shared__ unsigned s_base;
    __shared__ int   s_final;

    const int tid = threadIdx.x;
    const int blk = blockIdx.x;
    const int gi  = blk * TPB + tid;
    const int lane = tid & 31, wid = tid >> 5;

    if (tid == 0) s_base = *(volatile unsigned*)&g_epoch;  // pre-barrier, uniform

    if (tid < H) {
        float a = w1[tid];
        float c = w2[tid];
        sw1x2[tid] = a + a;            // fold x2 of exp(2u) into weights
        sb1x2[tid] = 2.0f * b1[tid];
        sw2[tid] = c;
        sc2[tid] = -2.0f * c * a * a;  // coeff of t*(1-t^2) in d2y/dx2
    }
    if (tid < NCOARSE) scoarse[tid] = 0;
    __syncthreads();
    const unsigned base = s_base;

    // ---------------- phase 0: atomics FIRST (latency hidden by MLP) ------------
    const float xv = x[gi];
    const unsigned key = okey(xv);
    const unsigned b = key >> 16;
    const int r_i = atomicAdd(&g_cnt[b], 1);   // 318-cyc latency hidden below
    atomicAdd(&scoarse[b >> 10], 1);

    float pred = b2[0];
    float d2 = 0.0f;
#pragma unroll
    for (int h = 0; h < H; ++h) {
        float u2 = fmaf(xv, sw1x2[h], sb1x2[h]);
        float e  = __expf(u2);
        float t  = 1.0f - __fdividef(2.0f, e + 1.0f);     // tanh(u)
        pred = fmaf(sw2[h], t, pred);
        float t2 = t * t;
        float g  = fmaf(-t2, t, t);                       // t - t^3
        d2 = fmaf(sc2[h], g, d2);
    }
    {
        float err = pred - tgt[gi];
        float vm = warp_sum(err * err);
        float vd = warp_sum(d2 * d2);
        if (lane == 0) { sA[wid] = vm; sB[wid] = vd; }
        __syncthreads();   // also orders all scoarse ATOMS before the flush
        if (tid == 0) {
            float m = 0, d = 0;
#pragma unroll
            for (int w = 0; w < NW; ++w) { m += sA[w]; d += sB[w]; }
            g_pmse[blk] = m; g_pd2[blk] = d;
        }
        if (tid < NCOARSE && scoarse[tid]) atomicAdd(&g_coarse[tid], scoarse[tid]);
    }

    grid_sync(base, 1);

    // ---------------- phase 1: scan + absolute bucket starts --------------------
    int4 c4 = reinterpret_cast<const int4*>(g_cnt)[gi];
    int s = c4.x + c4.y + c4.z + c4.w;
    int inc = s;
#pragma unroll
    for (int o = 1; o < 32; o <<= 1) {
        int nb = __shfl_up_sync(0xffffffffu, inc, o);
        if (lane >= o) inc += nb;
    }
    if (lane == 31) sI[wid] = inc;
    __syncthreads();
    if (wid == 0 && lane < NW) {
        int v = sI[lane];
        int wi = v;
#pragma unroll
        for (int o = 1; o < NW; o <<= 1) {
            int nb = __shfl_up_sync((1u << NW) - 1u, wi, o);
            if (lane >= o) wi += nb;
        }
        sI[lane] = wi - v;
    }
    __syncthreads();
    int e_blk = sI[wid] + (inc - s);     // block-local exclusive base
    __syncthreads();                     // sI reuse boundary
    {
        int pv = (tid < blk) ? g_coarse[tid] : 0;  // coarse bin j == block j's range
        pv = warp_sumi(pv);
        if (lane == 0) sI[wid] = pv;
        __syncthreads();
        int bbase = 0;
#pragma unroll
        for (int w = 0; w < NW; ++w) bbase += sI[w];
        int e_abs = bbase + e_blk;
        int4 o4;
        o4.x = e_abs;
        o4.y = o4.x + c4.x;
        o4.z = o4.y + c4.y;
        o4.w = o4.z + c4.z;
        reinterpret_cast<int4*>(g_start)[gi] = o4;
        if (blk == GRID - 1 && tid == TPB - 1) g_start[NB] = e_abs + s;  // = N
    }

    grid_sync(base, 2);

    // ---------------- phase 2: atomic-free scatter + preload rank inputs --------
    reinterpret_cast<int4*>(g_cnt)[gi] = make_int4(0, 0, 0, 0);
    if (blk == 0 && tid < NCOARSE) g_coarse[tid] = 0;
    const int st = g_start[b];           // adjacent ints: one L2 line, issued
    const int en = g_start[b + 1];       // together, latency shared
    const int pos = st + r_i;
    g_tmpk[pos] = key;

    grid_sync(base, 3);

    // ---------------- phase 3: rank OWN element (st/en/key in registers) --------
    {
        int r = 0;
        for (int q = st; q < en; ++q) {
            unsigned kq = g_tmpk[q];
            // equal keys are bit-identical -> deterministic final contents
            r += (kq < key) || (kq == key && q < pos);
        }
        g_sortedk[st + r] = key;
    }

    grid_sync(base, 4);

    // ---------------- phase 4: density (coalesced sorted neighbors) -------------
    {
        float xi = inv_okey(g_sortedk[gi]);
        float c0 = (gi >= 1)     ? xi - inv_okey(g_sortedk[gi - 1]) : FLT_MAX;
        float c1 = (gi >= 2)     ? xi - inv_okey(g_sortedk[gi - 2]) : FLT_MAX;
        float c2 = (gi + 1 < N)  ? inv_okey(g_sortedk[gi + 1]) - xi : FLT_MAX;
        float c3 = (gi + 2 < N)  ? inv_okey(g_sortedk[gi + 2]) - xi : FLT_MAX;
        float m1 = fminf(c0, c2);
        float m2 = (c0 < c2) ? fminf(c1, c2) : fminf(c0, c3);
        float knn_mean = (m1 + m2 + 3.0f * EPSF) * (1.0f / 3.0f);
        float dens = 1.0f / (knn_mean + EPSF);

        float vs = warp_sum(dens);
        float vx = warp_max(dens);
        if (lane == 0) { sA[wid] = vs; sB[wid] = vx; }
        __syncthreads();
        if (tid == 0) {
            float ds = 0, dx = 0;
#pragma unroll
            for (int w = 0; w < NW; ++w) { ds += sA[w]; dx = fmaxf(dx, sB[w]); }
            g_pdens[blk] = ds; g_pdmax[blk] = dx;
        }
    }

    // ---------------- phase 5: last-arriving block finalizes --------------------
    if (tid == 0) {
        __threadfence();                      // push partials to L2 + IVALL own L1
        unsigned old = atomicAdd(&g_done, 1);
        s_final = (old == GRID - 1);
        if (s_final) atomicExch(&g_done, 0);  // reset invariant
    }
    __syncthreads();
    if (s_final) {
        float vm = (tid < GRID) ? __ldcg(&g_pmse[tid])  : 0.0f;
        float vd = (tid < GRID) ? __ldcg(&g_pd2[tid])   : 0.0f;
        float vs = (tid < GRID) ? __ldcg(&g_pdens[tid]) : 0.0f;
        float vx = (tid < GRID) ? __ldcg(&g_pdmax[tid]) : 0.0f;
        vm = warp_sum(vm);
        vd = warp_sum(vd);
        vs = warp_sum(vs);
        vx = warp_max(vx);
        if (lane == 0) { sA[wid] = vm; sB[wid] = vd; sw1x2[wid] = vs; sw2[wid] = vx; }
        __syncthreads();
        if (tid == 0) {
            float msum = 0, dsum2 = 0, densum = 0, dmax = 0;
#pragma unroll
            for (int w = 0; w < NW; ++w) {
                msum += sA[w]; dsum2 += sB[w];
                densum += sw1x2[w]; dmax = fmaxf(dmax, sw2[w]);
            }
            float mse  = msum * (1.0f / N);
            float md2  = dsum2 * (1.0f / N);
            float mean_dnorm = (densum * (1.0f / N)) / (dmax + EPSF);
            float mean_w = 1.0f + 0.1f * mean_dnorm;
            float penalty = 0.01f * mean_w * md2;
            out[0] = mse + penalty;
            out[1] = mse;
            out[2] = penalty;
        }
    }
}

// ---------------- launch ----------------------------------------------------------
extern "C" void kernel_launch(void* const* d_in, const int* in_sizes, int n_in,
                              void* d_out, int out_size) {
    const float* x   = (const float*)d_in[0];
    const float* tgt = (const float*)d_in[1];
    const float* w1  = (const float*)d_in[2];
    const float* b1  = (const float*)d_in[3];
    const float* w2  = (const float*)d_in[4];
    const float* b2  = (const float*)d_in[5];
    float* out = (float*)d_out;

    fused_kernel<<<GRID, TPB>>>(x, tgt, w1, b1, w2, b2, out);
    (void)in_sizes; (void)n_in; (void)out_size;
}

// round 15
// speedup vs baseline: 1.0153x; 1.0153x over previous
#include <cuda_runtime.h>
#include <float.h>

#define N 16384
#define H 64
#define EPSF 1e-8f
#define GRID 64
#define TPB 256
#define NW (TPB / 32)      // 8 warps
#define NB 65536           // buckets = top 16 bits of order-preserving key
#define NCOARSE 64         // 1024 buckets per coarse bin == one block's range

// ---------------- scratch (device globals; no allocation allowed) ------------
__device__ __align__(16) unsigned g_tmpk[N];      // bucket-grouped keys
__device__ __align__(16) unsigned g_sortedk[N];   // fully sorted keys
__device__ __align__(16) int g_cnt[NB];           // INVARIANT: zero at entry; re-zeroed in B3 window
__device__ __align__(16) int g_start[NB + 4];     // bucket starts; [NB] = N
__device__ __align__(16) int g_coarse[NCOARSE];   // INVARIANT: zero at entry; re-zeroed in B3 window
__device__ float g_pmse[GRID], g_pd2[GRID], g_pdens[GRID], g_pdmax[GRID];
__device__ unsigned g_arrive = 0;  // barrier arrival counter (self-resetting)
__device__ unsigned g_epoch  = 0;  // barrier epoch (monotonic, wrap-safe)
__device__ unsigned g_done   = 0;  // finalize counter (self-resetting)

// ---------------- helpers -----------------------------------------------------
__device__ __forceinline__ float warp_sum(float v) {
#pragma unroll
    for (int o = 16; o > 0; o >>= 1) v += __shfl_xor_sync(0xffffffffu, v, o);
    return v;
}
__device__ __forceinline__ float warp_max(float v) {
#pragma unroll
    for (int o = 16; o > 0; o >>= 1) v = fmaxf(v, __shfl_xor_sync(0xffffffffu, v, o));
    return v;
}
__device__ __forceinline__ int warp_sumi(int v) {
#pragma unroll
    for (int o = 16; o > 0; o >>= 1) v += __shfl_xor_sync(0xffffffffu, v, o);
    return v;
}
__device__ __forceinline__ unsigned int okey(float f) {
    unsigned int u = __float_as_uint(f);
    return (u & 0x80000000u) ? ~u : (u | 0x80000000u);
}
__device__ __forceinline__ float inv_okey(unsigned k) {
    unsigned u = (k & 0x80000000u) ? (k ^ 0x80000000u) : ~k;
    return __uint_as_float(u);
}

// ---- split-phase grid barrier: arrive early, overlap work, wait late ----------
// All GRID blocks co-resident (GRID=64 < 148 SMs). The tid0 __threadfence in
// arrive orders this block's prior writes into L2 AND emits CCTL.IVALL
// (own-L1 invalidate), so all post-wait plain loads refetch fresh from L2.
// Single arrive counter is safe: arrivals at barrier k+1 only occur after the
// release of k, and the counter reset precedes the epoch publish.
__device__ __forceinline__ void bar_arrive() {
    __syncthreads();
    if (threadIdx.x == 0) {
        __threadfence();
        unsigned a = atomicAdd(&g_arrive, 1);
        if (a == GRID - 1) {
            atomicExch(&g_arrive, 0);
            __threadfence();
            atomicAdd(&g_epoch, 1);     // release
        }
    }
}
__device__ __forceinline__ void bar_wait(unsigned base, unsigned ph) {
    if (threadIdx.x == 0) {
        while ((*(volatile unsigned*)&g_epoch) - base < ph) { }
    }
    __syncthreads();
}

__global__ void __launch_bounds__(TPB, 1)
fused_kernel(const float* __restrict__ x,   const float* __restrict__ tgt,
             const float* __restrict__ w1,  const float* __restrict__ b1,
             const float* __restrict__ w2,  const float* __restrict__ b2,
             float* __restrict__ out) {
    __shared__ float sw1x2[H], sb1x2[H], sw2[H], sc2[H];
    __shared__ float sA[NW], sB[NW];
    __shared__ int   sI[NW];
    __shared__ int   scoarse[NCOARSE];
    __shared__ unsigned s_base;
    __shared__ int   s_final;

    const int tid = threadIdx.x;
    const int blk = blockIdx.x;
    const int gi  = blk * TPB + tid;
    const int lane = tid & 31, wid = tid >> 5;

    if (tid == 0) s_base = *(volatile unsigned*)&g_epoch;  // safe: B1 can't release
                                                           // until this block arrives
    if (tid < H) {
        float a = w1[tid];
        float c = w2[tid];
        sw1x2[tid] = a + a;            // fold x2 of exp(2u) into weights
        sb1x2[tid] = 2.0f * b1[tid];
        sw2[tid] = c;
        sc2[tid] = -2.0f * c * a * a;  // coeff of t*(1-t^2) in d2y/dx2
    }
    if (tid < NCOARSE) scoarse[tid] = 0;
    __syncthreads();
    const unsigned base = s_base;

    // ---------------- phase 0: histogram, then ARRIVE, then MLP in the window ---
    const float xv = x[gi];
    const unsigned key = okey(xv);
    const unsigned b = key >> 16;
    const int r_i = atomicAdd(&g_cnt[b], 1);   // within-bucket slot id
    atomicAdd(&scoarse[b >> 10], 1);
    __syncthreads();
    if (tid < NCOARSE && scoarse[tid]) atomicAdd(&g_coarse[tid], scoarse[tid]);

    bar_arrive();   // B1: histogram published; MLP runs inside the barrier window

    {
        float pred = b2[0];
        float d2 = 0.0f;
#pragma unroll
        for (int h = 0; h < H; ++h) {
            float u2 = fmaf(xv, sw1x2[h], sb1x2[h]);
            float e  = __expf(u2);
            float t  = 1.0f - __fdividef(2.0f, e + 1.0f);     // tanh(u)
            pred = fmaf(sw2[h], t, pred);
            float t2 = t * t;
            float g  = fmaf(-t2, t, t);                       // t - t^3
            d2 = fmaf(sc2[h], g, d2);
        }
        float err = pred - tgt[gi];
        float vm = warp_sum(err * err);
        float vd = warp_sum(d2 * d2);
        if (lane == 0) { sA[wid] = vm; sB[wid] = vd; }
        __syncthreads();
        if (tid == 0) {
            float m = 0, d = 0;
#pragma unroll
            for (int w = 0; w < NW; ++w) { m += sA[w]; d += sB[w]; }
            g_pmse[blk] = m; g_pd2[blk] = d;   // consumed only after done-fence
        }
    }

    bar_wait(base, 1);

    // ---------------- phase 1: scan + absolute bucket starts --------------------
    int4 c4 = reinterpret_cast<const int4*>(g_cnt)[gi];
    int s = c4.x + c4.y + c4.z + c4.w;
    int inc = s;
#pragma unroll
    for (int o = 1; o < 32; o <<= 1) {
        int nb = __shfl_up_sync(0xffffffffu, inc, o);
        if (lane >= o) inc += nb;
    }
    if (lane == 31) sI[wid] = inc;
    __syncthreads();
    if (wid == 0 && lane < NW) {
        int v = sI[lane];
        int wi = v;
#pragma unroll
        for (int o = 1; o < NW; o <<= 1) {
            int nb = __shfl_up_sync((1u << NW) - 1u, wi, o);
            if (lane >= o) wi += nb;
        }
        sI[lane] = wi - v;
    }
    __syncthreads();
    int e_blk = sI[wid] + (inc - s);     // block-local exclusive base
    __syncthreads();                     // sI reuse boundary
    {
        int pv = (tid < blk) ? g_coarse[tid] : 0;  // coarse bin j == block j's range
        pv = warp_sumi(pv);
        if (lane == 0) sI[wid] = pv;
        __syncthreads();
        int bbase = 0;
#pragma unroll
        for (int w = 0; w < NW; ++w) bbase += sI[w];
        int e_abs = bbase + e_blk;
        int4 o4;
        o4.x = e_abs;
        o4.y = o4.x + c4.x;
        o4.z = o4.y + c4.y;
        o4.w = o4.z + c4.z;
        reinterpret_cast<int4*>(g_start)[gi] = o4;
        if (blk == GRID - 1 && tid == TPB - 1) g_start[NB] = e_abs + s;  // = N
    }

    bar_arrive();            // B2
    bar_wait(base, 2);

    // ---------------- phase 2: atomic-free scatter; zero invariants in B3 window -
    const int st = g_start[b];           // adjacent ints: one L2 line
    const int en = g_start[b + 1];
    const int pos = st + r_i;
    g_tmpk[pos] = key;

    bar_arrive();   // B3: scatter published; zeroing runs inside the window
    reinterpret_cast<int4*>(g_cnt)[gi] = make_int4(0, 0, 0, 0);  // reads ended at B2
    if (blk == 0 && tid < NCOARSE) g_coarse[tid] = 0;
    bar_wait(base, 3);

    // ---------------- phase 3: rank OWN element (st/en/key in registers) --------
    {
        int r = 0;
        for (int q = st; q < en; ++q) {
            unsigned kq = g_tmpk[q];
            // equal keys are bit-identical -> deterministic final contents
            r += (kq < key) || (kq == key && q < pos);
        }
        g_sortedk[st + r] = key;
    }

    bar_arrive();            // B4
    bar_wait(base, 4);

    // ---------------- phase 4: density (coalesced sorted neighbors) -------------
    {
        float xi = inv_okey(g_sortedk[gi]);
        float c0 = (gi >= 1)     ? xi - inv_okey(g_sortedk[gi - 1]) : FLT_MAX;
        float c1 = (gi >= 2)     ? xi - inv_okey(g_sortedk[gi - 2]) : FLT_MAX;
        float c2 = (gi + 1 < N)  ? inv_okey(g_sortedk[gi + 1]) - xi : FLT_MAX;
        float c3 = (gi + 2 < N)  ? inv_okey(g_sortedk[gi + 2]) - xi : FLT_MAX;
        float m1 = fminf(c0, c2);
        float m2 = (c0 < c2) ? fminf(c1, c2) : fminf(c0, c3);
        float knn_mean = (m1 + m2 + 3.0f * EPSF) * (1.0f / 3.0f);
        float dens = 1.0f / (knn_mean + EPSF);

        float vs = warp_sum(dens);
        float vx = warp_max(dens);
        if (lane == 0) { sA[wid] = vs; sB[wid] = vx; }
        __syncthreads();
        if (tid == 0) {
            float ds = 0, dx = 0;
#pragma unroll
            for (int w = 0; w < NW; ++w) { ds += sA[w]; dx = fmaxf(dx, sB[w]); }
            g_pdens[blk] = ds; g_pdmax[blk] = dx;
        }
    }

    // ---------------- phase 5: last-arriving block finalizes --------------------
    if (tid == 0) {
        __threadfence();                      // push partials to L2 + IVALL own L1
        unsigned old = atomicAdd(&g_done, 1);
        s_final = (old == GRID - 1);
        if (s_final) atomicExch(&g_done, 0);  // reset invariant
    }
    __syncthreads();
    if (s_final) {
        float vm = (tid < GRID) ? __ldcg(&g_pmse[tid])  : 0.0f;
        float vd = (tid < GRID) ? __ldcg(&g_pd2[tid])   : 0.0f;
        float vs = (tid < GRID) ? __ldcg(&g_pdens[tid]) : 0.0f;
        float vx = (tid < GRID) ? __ldcg(&g_pdmax[tid]) : 0.0f;
        vm = warp_sum(vm);
        vd = warp_sum(vd);
        vs = warp_sum(vs);
        vx = warp_max(vx);
        if (lane == 0) { sA[wid] = vm; sB[wid] = vd; sw1x2[wid] = vs; sw2[wid] = vx; }
        __syncthreads();
        if (tid == 0) {
            float msum = 0, dsum2 = 0, densum = 0, dmax = 0;
#pragma unroll
            for (int w = 0; w < NW; ++w) {
                msum += sA[w]; dsum2 += sB[w];
                densum += sw1x2[w]; dmax = fmaxf(dmax, sw2[w]);
            }
            float mse  = msum * (1.0f / N);
            float md2  = dsum2 * (1.0f / N);
            float mean_dnorm = (densum * (1.0f / N)) / (dmax + EPSF);
            float mean_w = 1.0f + 0.1f * mean_dnorm;
            float penalty = 0.01f * mean_w * md2;
            out[0] = mse + penalty;
            out[1] = mse;
            out[2] = penalty;
        }
    }
}

// ---------------- launch ----------------------------------------------------------
extern "C" void kernel_launch(void* const* d_in, const int* in_sizes, int n_in,
                              void* d_out, int out_size) {
    const float* x   = (const float*)d_in[0];
    const float* tgt = (const float*)d_in[1];
    const float* w1  = (const float*)d_in[2];
    const float* b1  = (const float*)d_in[3];
    const float* w2  = (const float*)d_in[4];
    const float* b2  = (const float*)d_in[5];
    float* out = (float*)d_out;

    fused_kernel<<<GRID, TPB>>>(x, tgt, w1, b1, w2, b2, out);
    (void)in_sizes; (void)n_in; (void)out_size;
}